// round 7
// baseline (speedup 1.0000x reference)
#include <cuda_runtime.h>
#include <cuda_fp16.h>

// Problem constants (fixed by the dataset)
#define F_DIM   128
#define MAXN    10240
#define MAXE    655360
#define ATT_SCALE 0.17677669529663687f   // 1/sqrt(32)
#define LN_EPS  1e-5f

// ---------------- scratch (device globals; no allocation allowed) -------------
__device__ float  g_Q[MAXN * F_DIM];
// interleaved KV: per node 256 halfs; lane l: K dims[4l..4l+4) at half-offset 8l,
// V dims[4l..4l+4) at half-offset 8l+4  -> one uint4 per lane per edge.
__device__ __half g_KV[MAXN * 256];
__device__ float  g_R[MAXN * F_DIM];
__device__ int    g_counts[MAXN];
__device__ int    g_offs[MAXN + 1];
__device__ int    g_cursor[MAXN];
__device__ int    g_srcsorted[MAXE];

// ---------------- packed fp32x2 helpers (Blackwell) ----------------------------
__device__ __forceinline__ unsigned long long fma2(
    unsigned long long a, unsigned long long b, unsigned long long c) {
    unsigned long long d;
    asm("fma.rn.f32x2 %0, %1, %2, %3;" : "=l"(d) : "l"(a), "l"(b), "l"(c));
    return d;
}
__device__ __forceinline__ unsigned long long pack2(float lo, float hi) {
    unsigned long long d;
    asm("mov.b64 %0, {%1, %2};" : "=l"(d) : "f"(lo), "f"(hi));
    return d;
}
__device__ __forceinline__ void unpack2(unsigned long long v, float& lo, float& hi) {
    asm("mov.b64 {%0, %1}, %2;" : "=f"(lo), "=f"(hi) : "l"(v));
}

// ---------------- K1: fused Q/K/V/R projections + dst histogram ----------------
// One block = 32 nodes, 128 threads (thread t = output column). Weight matrices
// are each read ONCE per block (half the traffic of the 16-node tile). The
// f-loop runs twice: pass 1 (Q,K), pass 2 (V,R) — halves live accumulators
// to 32 u64 (=64 regs), keeping register pressure safe.
__global__ __launch_bounds__(128) void k_qkvr(
    const float* __restrict__ X,
    const float* __restrict__ WQ, const float* __restrict__ WK,
    const float* __restrict__ WV, const float* __restrict__ WR,
    const float* __restrict__ br,
    const int* __restrict__ dst, int N, int E, int epb)
{
    __shared__ float xs[F_DIM][32];      // xs[f][i] = X[n0+i][f]
    const int n0 = blockIdx.x * 32;
    const int t  = threadIdx.x;          // output column 0..127

    for (int i = 0; i < 32; ++i) {
        int n = n0 + i;
        xs[t][i] = (n < N) ? X[n * F_DIM + t] : 0.f;
    }
    __syncthreads();

    const int kvoff = ((t >> 2) << 3) + (t & 3);   // K slot; V slot = +4

    // ---------------- pass 1: Q and K ----------------
    {
        unsigned long long aq[16], ak[16];
        #pragma unroll
        for (int j = 0; j < 16; ++j) { aq[j] = ak[j] = 0ull; }

        #pragma unroll 2
        for (int f = 0; f < F_DIM; ++f) {
            const float wq = __ldg(&WQ[f * F_DIM + t]);
            const float wk = __ldg(&WK[f * F_DIM + t]);
            const unsigned long long wq2 = pack2(wq, wq);
            const unsigned long long wk2 = pack2(wk, wk);
            #pragma unroll
            for (int j = 0; j < 16; ++j) {
                const unsigned long long x2 =
                    *reinterpret_cast<const unsigned long long*>(&xs[f][2 * j]);
                aq[j] = fma2(x2, wq2, aq[j]);
                ak[j] = fma2(x2, wk2, ak[j]);
            }
        }

        #pragma unroll
        for (int j = 0; j < 16; ++j) {
            float qlo, qhi, klo, khi;
            unpack2(aq[j], qlo, qhi);
            unpack2(ak[j], klo, khi);
            const int nA = n0 + 2 * j, nB = nA + 1;
            if (nA < N) {
                g_Q[nA * F_DIM + t]    = qlo;
                g_KV[nA * 256 + kvoff] = __float2half_rn(klo);
            }
            if (nB < N) {
                g_Q[nB * F_DIM + t]    = qhi;
                g_KV[nB * 256 + kvoff] = __float2half_rn(khi);
            }
        }
    }

    // ---------------- pass 2: V and R ----------------
    {
        unsigned long long av[16], ar[16];
        #pragma unroll
        for (int j = 0; j < 16; ++j) { av[j] = ar[j] = 0ull; }

        #pragma unroll 2
        for (int f = 0; f < F_DIM; ++f) {
            const float wv = __ldg(&WV[f * F_DIM + t]);
            const float wr = __ldg(&WR[f * F_DIM + t]);
            const unsigned long long wv2 = pack2(wv, wv);
            const unsigned long long wr2 = pack2(wr, wr);
            #pragma unroll
            for (int j = 0; j < 16; ++j) {
                const unsigned long long x2 =
                    *reinterpret_cast<const unsigned long long*>(&xs[f][2 * j]);
                av[j] = fma2(x2, wv2, av[j]);
                ar[j] = fma2(x2, wr2, ar[j]);
            }
        }

        const float b = __ldg(&br[t]);
        #pragma unroll
        for (int j = 0; j < 16; ++j) {
            float vlo, vhi, rlo, rhi;
            unpack2(av[j], vlo, vhi);
            unpack2(ar[j], rlo, rhi);
            const int nA = n0 + 2 * j, nB = nA + 1;
            if (nA < N) {
                g_KV[nA * 256 + kvoff + 4] = __float2half_rn(vlo);
                g_R[nA * F_DIM + t]        = rlo + b;
            }
            if (nB < N) {
                g_KV[nB * 256 + kvoff + 4] = __float2half_rn(vhi);
                g_R[nB * F_DIM + t]        = rhi + b;
            }
        }
    }

    // fused dst histogram: this block's edge slice
    const int e0 = blockIdx.x * epb;
    const int e1 = min(e0 + epb, E);
    for (int e = e0 + t; e < e1; e += 128)
        atomicAdd(&g_counts[__ldg(&dst[e])], 1);
}

// ---------------- K2: exclusive scan (warp-shuffle, 2 barriers) ----------------
__global__ __launch_bounds__(1024) void k_scan(int N, int E) {
    __shared__ int wsum[32];
    const int t = threadIdx.x;
    const int lane = t & 31, w = t >> 5;
    const int base = t * 10;             // 1024*10 = 10240 >= MAXN

    int loc[10];
    int s = 0;
    #pragma unroll
    for (int i = 0; i < 10; ++i) {
        const int idx = base + i;
        loc[i] = (idx < N) ? g_counts[idx] : 0;
        s += loc[i];
    }
    int inc = s;
    #pragma unroll
    for (int o = 1; o < 32; o <<= 1) {
        int v = __shfl_up_sync(0xffffffffu, inc, o);
        if (lane >= o) inc += v;
    }
    if (lane == 31) wsum[w] = inc;
    __syncthreads();
    if (w == 0) {
        int v = wsum[lane];
        #pragma unroll
        for (int o = 1; o < 32; o <<= 1) {
            int u = __shfl_up_sync(0xffffffffu, v, o);
            if (lane >= o) v += u;
        }
        wsum[lane] = v;
    }
    __syncthreads();
    int run = ((w == 0) ? 0 : wsum[w - 1]) + (inc - s);  // exclusive prefix
    #pragma unroll
    for (int i = 0; i < 10; ++i) {
        const int idx = base + i;
        if (idx < N) { g_offs[idx] = run; g_cursor[idx] = run; run += loc[i]; }
    }
    if (t == 0) g_offs[N] = E;
}

// ---------------- K3: scatter edges into CSR order (ILP x4) --------------------
__global__ __launch_bounds__(256) void k_scatter(
    const int* __restrict__ src, const int* __restrict__ dst, int E)
{
    const int base = (blockIdx.x * blockDim.x + threadIdx.x) * 4;
    if (base + 3 < E) {
        const int4 d = *reinterpret_cast<const int4*>(dst + base);
        const int4 s = *reinterpret_cast<const int4*>(src + base);
        const int p0 = atomicAdd(&g_cursor[d.x], 1);
        const int p1 = atomicAdd(&g_cursor[d.y], 1);
        const int p2 = atomicAdd(&g_cursor[d.z], 1);
        const int p3 = atomicAdd(&g_cursor[d.w], 1);
        g_srcsorted[p0] = s.x;
        g_srcsorted[p1] = s.y;
        g_srcsorted[p2] = s.z;
        g_srcsorted[p3] = s.w;
    } else {
        for (int e = base; e < E; ++e) {
            const int pos = atomicAdd(&g_cursor[dst[e]], 1);
            g_srcsorted[pos] = src[e];
        }
    }
}

// ---------------- K4: fused attention + residual + LayerNorm -------------------
// One warp per destination node; lane l owns dims [4l, 4l+4); head = l/8.
// One uint4 gather per edge per lane (interleaved K|V). Inner loop unrolled x4.
// (round-4 version: measured 49.4us)
__global__ __launch_bounds__(256) void k_attn(
    const float* __restrict__ gamma, const float* __restrict__ beta,
    float* __restrict__ out, int N)
{
    const int warp = (blockIdx.x * blockDim.x + threadIdx.x) >> 5;
    if (warp >= N) return;
    const int lane = threadIdx.x & 31;

    float4 q = ((const float4*)g_Q)[warp * 32 + lane];
    q.x *= ATT_SCALE; q.y *= ATT_SCALE; q.z *= ATT_SCALE; q.w *= ATT_SCALE;

    const uint4* __restrict__ KV = (const uint4*)g_KV;   // 32 uint4 per node

    float4 acc = make_float4(0.f, 0.f, 0.f, 0.f);
    float ssum = 0.f;

    const int beg = g_offs[warp];
    const int end = g_offs[warp + 1];

    for (int base = beg; base < end; base += 32) {
        const int idx = base + lane;
        const int mysrc = (idx < end) ? g_srcsorted[idx] : 0;
        const int cnt = min(32, end - base);
        int j = 0;
        for (; j + 4 <= cnt; j += 4) {
            const int s0 = __shfl_sync(0xffffffffu, mysrc, j);
            const int s1 = __shfl_sync(0xffffffffu, mysrc, j + 1);
            const int s2 = __shfl_sync(0xffffffffu, mysrc, j + 2);
            const int s3 = __shfl_sync(0xffffffffu, mysrc, j + 3);
            const uint4 u0 = __ldg(&KV[s0 * 32 + lane]);
            const uint4 u1 = __ldg(&KV[s1 * 32 + lane]);
            const uint4 u2 = __ldg(&KV[s2 * 32 + lane]);
            const uint4 u3 = __ldg(&KV[s3 * 32 + lane]);
            #pragma unroll
            for (int e = 0; e < 4; ++e) {
                const uint4 u = (e == 0) ? u0 : (e == 1) ? u1 : (e == 2) ? u2 : u3;
                const float2 k0 = __half22float2(*(const __half2*)&u.x);
                const float2 k1 = __half22float2(*(const __half2*)&u.y);
                float p = q.x * k0.x + q.y * k0.y + q.z * k1.x + q.w * k1.y;
                p += __shfl_xor_sync(0xffffffffu, p, 1);
                p += __shfl_xor_sync(0xffffffffu, p, 2);
                p += __shfl_xor_sync(0xffffffffu, p, 4);
                const float wgt = __expf(p);
                const float2 v0 = __half22float2(*(const __half2*)&u.z);
                const float2 v1 = __half22float2(*(const __half2*)&u.w);
                ssum += wgt;
                acc.x = fmaf(wgt, v0.x, acc.x);
                acc.y = fmaf(wgt, v0.y, acc.y);
                acc.z = fmaf(wgt, v1.x, acc.z);
                acc.w = fmaf(wgt, v1.y, acc.w);
            }
        }
        for (; j < cnt; ++j) {
            const int s0 = __shfl_sync(0xffffffffu, mysrc, j);
            const uint4 u = __ldg(&KV[s0 * 32 + lane]);
            const float2 k0 = __half22float2(*(const __half2*)&u.x);
            const float2 k1 = __half22float2(*(const __half2*)&u.y);
            float p = q.x * k0.x + q.y * k0.y + q.z * k1.x + q.w * k1.y;
            p += __shfl_xor_sync(0xffffffffu, p, 1);
            p += __shfl_xor_sync(0xffffffffu, p, 2);
            p += __shfl_xor_sync(0xffffffffu, p, 4);
            const float wgt = __expf(p);
            const float2 v0 = __half22float2(*(const __half2*)&u.z);
            const float2 v1 = __half22float2(*(const __half2*)&u.w);
            ssum += wgt;
            acc.x = fmaf(wgt, v0.x, acc.x);
            acc.y = fmaf(wgt, v0.y, acc.y);
            acc.z = fmaf(wgt, v1.x, acc.z);
            acc.w = fmaf(wgt, v1.y, acc.w);
        }
    }

    const float inv = 1.f / (ssum + 1e-12f);
    const float4 r = ((const float4*)g_R)[warp * 32 + lane];
    float4 h;
    h.x = fmaf(acc.x, inv, r.x);
    h.y = fmaf(acc.y, inv, r.y);
    h.z = fmaf(acc.z, inv, r.z);
    h.w = fmaf(acc.w, inv, r.w);

    float s1 = h.x + h.y + h.z + h.w;
    float s2 = h.x * h.x + h.y * h.y + h.z * h.z + h.w * h.w;
    #pragma unroll
    for (int o = 16; o; o >>= 1) {
        s1 += __shfl_xor_sync(0xffffffffu, s1, o);
        s2 += __shfl_xor_sync(0xffffffffu, s2, o);
    }
    const float mu  = s1 * (1.f / 128.f);
    const float var = s2 * (1.f / 128.f) - mu * mu;
    const float rs  = rsqrtf(var + LN_EPS);

    const float4 g = ((const float4*)gamma)[lane];
    const float4 b = ((const float4*)beta)[lane];
    float4 o4;
    o4.x = fmaf(g.x * (h.x - mu), rs, b.x);
    o4.y = fmaf(g.y * (h.y - mu), rs, b.y);
    o4.z = fmaf(g.z * (h.z - mu), rs, b.z);
    o4.w = fmaf(g.w * (h.w - mu), rs, b.w);
    ((float4*)out)[warp * 32 + lane] = o4;
}

// ---------------- launch -------------------------------------------------------
extern "C" void kernel_launch(void* const* d_in, const int* in_sizes, int n_in,
                              void* d_out, int out_size)
{
    const float* nodes = (const float*)d_in[0];
    const float* WQ    = (const float*)d_in[1];
    const float* WK    = (const float*)d_in[2];
    const float* WV    = (const float*)d_in[3];
    const float* WR    = (const float*)d_in[4];
    const float* br    = (const float*)d_in[5];
    const float* gamma = (const float*)d_in[6];
    const float* beta  = (const float*)d_in[7];
    const int*   ei    = (const int*)d_in[8];

    const int N = in_sizes[0] / F_DIM;
    const int E = in_sizes[8] / 2;
    const int* src = ei;
    const int* dst = ei + E;

    const int nblk = (N + 31) / 32;
    const int epb  = (E + nblk - 1) / nblk;

    void* cnt_ptr = nullptr;
    cudaGetSymbolAddress(&cnt_ptr, g_counts);
    cudaMemsetAsync(cnt_ptr, 0, N * sizeof(int));

    k_qkvr<<<nblk, 128>>>(nodes, WQ, WK, WV, WR, br, dst, N, E, epb);
    k_scan<<<1, 1024>>>(N, E);
    k_scatter<<<((E + 3) / 4 + 255) / 256, 256>>>(src, dst, E);
    k_attn<<<(N + 7) / 8, 256>>>(gamma, beta, (float*)d_out, N);
}

// round 8
// speedup vs baseline: 1.1670x; 1.1670x over previous
#include <cuda_runtime.h>
#include <cuda_fp16.h>

// Problem constants (fixed by the dataset)
#define F_DIM   128
#define MAXN    10240
#define MAXE    655360
#define ATT_SCALE 0.17677669529663687f   // 1/sqrt(32)
#define LN_EPS  1e-5f

// ---------------- scratch (device globals; no allocation allowed) -------------
__device__ float  g_Q[MAXN * F_DIM];
__device__ __half g_KV[MAXN * 256];      // per node: 128 K halfs then 128 V halfs
__device__ float  g_R[MAXN * F_DIM];
__device__ int    g_counts[MAXN];
__device__ int    g_offs[MAXN + 1];
__device__ int    g_cursor[MAXN];
__device__ int    g_srcsorted[MAXE];

// ---------------- packed fp32x2 helpers (Blackwell) ----------------------------
__device__ __forceinline__ unsigned long long fma2(
    unsigned long long a, unsigned long long b, unsigned long long c) {
    unsigned long long d;
    asm("fma.rn.f32x2 %0, %1, %2, %3;" : "=l"(d) : "l"(a), "l"(b), "l"(c));
    return d;
}
__device__ __forceinline__ unsigned long long pack2(float lo, float hi) {
    unsigned long long d;
    asm("mov.b64 %0, {%1, %2};" : "=l"(d) : "f"(lo), "f"(hi));
    return d;
}
__device__ __forceinline__ void unpack2(unsigned long long v, float& lo, float& hi) {
    asm("mov.b64 {%0, %1}, %2;" : "=f"(lo), "=f"(hi) : "l"(v));
}

// ---------------- K1: fused Q/K/V/R projections + dst histogram ----------------
// One block = 16 nodes, 128 threads (thread t = output column).
// Accumulators held as packed f32x2 pairs (nodes 2j, 2j+1); FFMA2 inner loop.
// Contiguous half stores for K and V (coalesced). (R3 version, best measured.)
__global__ __launch_bounds__(128) void k_qkvr(
    const float* __restrict__ X,
    const float* __restrict__ WQ, const float* __restrict__ WK,
    const float* __restrict__ WV, const float* __restrict__ WR,
    const float* __restrict__ br,
    const int* __restrict__ dst, int N, int E, int epb)
{
    __shared__ float xs[F_DIM][16];      // xs[f][i] = X[n0+i][f]
    const int n0 = blockIdx.x * 16;
    const int t  = threadIdx.x;          // output column 0..127

    #pragma unroll
    for (int i = 0; i < 16; ++i) {
        int n = n0 + i;
        xs[t][i] = (n < N) ? X[n * F_DIM + t] : 0.f;
    }
    __syncthreads();

    unsigned long long aq[8], ak[8], av[8], ar[8];
    #pragma unroll
    for (int j = 0; j < 8; ++j) { aq[j] = ak[j] = av[j] = ar[j] = 0ull; }

    #pragma unroll 4
    for (int f = 0; f < F_DIM; ++f) {
        const float wq = __ldg(&WQ[f * F_DIM + t]);
        const float wk = __ldg(&WK[f * F_DIM + t]);
        const float wv = __ldg(&WV[f * F_DIM + t]);
        const float wr = __ldg(&WR[f * F_DIM + t]);
        const unsigned long long wq2 = pack2(wq, wq);
        const unsigned long long wk2 = pack2(wk, wk);
        const unsigned long long wv2 = pack2(wv, wv);
        const unsigned long long wr2 = pack2(wr, wr);
        #pragma unroll
        for (int j = 0; j < 8; ++j) {
            const unsigned long long x2 =
                *reinterpret_cast<const unsigned long long*>(&xs[f][2 * j]);
            aq[j] = fma2(x2, wq2, aq[j]);
            ak[j] = fma2(x2, wk2, ak[j]);
            av[j] = fma2(x2, wv2, av[j]);
            ar[j] = fma2(x2, wr2, ar[j]);
        }
    }

    const float b = __ldg(&br[t]);
    #pragma unroll
    for (int j = 0; j < 8; ++j) {
        float qlo, qhi, klo, khi, vlo, vhi, rlo, rhi;
        unpack2(aq[j], qlo, qhi);
        unpack2(ak[j], klo, khi);
        unpack2(av[j], vlo, vhi);
        unpack2(ar[j], rlo, rhi);
        const int nA = n0 + 2 * j, nB = nA + 1;
        if (nA < N) {
            g_Q[nA * F_DIM + t]      = qlo;
            g_KV[nA * 256 + t]       = __float2half_rn(klo);
            g_KV[nA * 256 + 128 + t] = __float2half_rn(vlo);
            g_R[nA * F_DIM + t]      = rlo + b;
        }
        if (nB < N) {
            g_Q[nB * F_DIM + t]      = qhi;
            g_KV[nB * 256 + t]       = __float2half_rn(khi);
            g_KV[nB * 256 + 128 + t] = __float2half_rn(vhi);
            g_R[nB * F_DIM + t]      = rhi + b;
        }
    }

    // fused dst histogram: this block's edge slice
    const int e0 = blockIdx.x * epb;
    const int e1 = min(e0 + epb, E);
    for (int e = e0 + t; e < e1; e += 128)
        atomicAdd(&g_counts[dst[e]], 1);
}

// ---------------- K2: exclusive scan (warp-shuffle, 2 barriers) ----------------
__global__ __launch_bounds__(1024) void k_scan(int N, int E) {
    __shared__ int wsum[32];
    const int t = threadIdx.x;
    const int lane = t & 31, w = t >> 5;
    const int base = t * 10;             // 1024*10 = 10240 >= MAXN

    int loc[10];
    int s = 0;
    #pragma unroll
    for (int i = 0; i < 10; ++i) {
        const int idx = base + i;
        loc[i] = (idx < N) ? g_counts[idx] : 0;
        s += loc[i];
    }
    int inc = s;
    #pragma unroll
    for (int o = 1; o < 32; o <<= 1) {
        int v = __shfl_up_sync(0xffffffffu, inc, o);
        if (lane >= o) inc += v;
    }
    if (lane == 31) wsum[w] = inc;
    __syncthreads();
    if (w == 0) {
        int v = wsum[lane];
        #pragma unroll
        for (int o = 1; o < 32; o <<= 1) {
            int u = __shfl_up_sync(0xffffffffu, v, o);
            if (lane >= o) v += u;
        }
        wsum[lane] = v;
    }
    __syncthreads();
    int run = ((w == 0) ? 0 : wsum[w - 1]) + (inc - s);  // exclusive prefix
    #pragma unroll
    for (int i = 0; i < 10; ++i) {
        const int idx = base + i;
        if (idx < N) { g_offs[idx] = run; g_cursor[idx] = run; run += loc[i]; }
    }
    if (t == 0) g_offs[N] = E;
}

// ---------------- K3: scatter edges into CSR order (ILP x4, measured win) ------
__global__ __launch_bounds__(256) void k_scatter(
    const int* __restrict__ src, const int* __restrict__ dst, int E)
{
    const int base = (blockIdx.x * blockDim.x + threadIdx.x) * 4;
    if (base + 3 < E) {
        const int4 d = *reinterpret_cast<const int4*>(dst + base);
        const int4 s = *reinterpret_cast<const int4*>(src + base);
        const int p0 = atomicAdd(&g_cursor[d.x], 1);
        const int p1 = atomicAdd(&g_cursor[d.y], 1);
        const int p2 = atomicAdd(&g_cursor[d.z], 1);
        const int p3 = atomicAdd(&g_cursor[d.w], 1);
        g_srcsorted[p0] = s.x;
        g_srcsorted[p1] = s.y;
        g_srcsorted[p2] = s.z;
        g_srcsorted[p3] = s.w;
    } else {
        for (int e = base; e < E; ++e) {
            const int pos = atomicAdd(&g_cursor[dst[e]], 1);
            g_srcsorted[pos] = src[e];
        }
    }
}

// ---------------- K4: fused attention + residual + LayerNorm (R3 version) ------
// One warp per destination node; lane l owns dims [4l, 4l+4); head = l/8.
__global__ __launch_bounds__(256) void k_attn(
    const float* __restrict__ gamma, const float* __restrict__ beta,
    float* __restrict__ out, int N)
{
    const int warp = (blockIdx.x * blockDim.x + threadIdx.x) >> 5;
    if (warp >= N) return;
    const int lane = threadIdx.x & 31;

    float4 q = ((const float4*)g_Q)[warp * 32 + lane];
    q.x *= ATT_SCALE; q.y *= ATT_SCALE; q.z *= ATT_SCALE; q.w *= ATT_SCALE;

    const uint2* __restrict__ KV = (const uint2*)g_KV;   // 64 uint2 per node row

    float4 acc = make_float4(0.f, 0.f, 0.f, 0.f);
    float ssum = 0.f;

    const int beg = g_offs[warp];
    const int end = g_offs[warp + 1];

    for (int base = beg; base < end; base += 32) {
        const int idx = base + lane;
        const int mysrc = (idx < end) ? g_srcsorted[idx] : 0;
        const int cnt = min(32, end - base);
        for (int j = 0; j < cnt; ++j) {
            const int src = __shfl_sync(0xffffffffu, mysrc, j);
            const uint2 ku = KV[src * 64 + lane];
            const uint2 vu = KV[src * 64 + 32 + lane];
            const float2 k0 = __half22float2(*(const __half2*)&ku.x);
            const float2 k1 = __half22float2(*(const __half2*)&ku.y);
            float p = q.x * k0.x + q.y * k0.y + q.z * k1.x + q.w * k1.y;
            p += __shfl_xor_sync(0xffffffffu, p, 1);
            p += __shfl_xor_sync(0xffffffffu, p, 2);
            p += __shfl_xor_sync(0xffffffffu, p, 4);
            const float wgt = __expf(p);
            const float2 v0 = __half22float2(*(const __half2*)&vu.x);
            const float2 v1 = __half22float2(*(const __half2*)&vu.y);
            ssum += wgt;
            acc.x = fmaf(wgt, v0.x, acc.x);
            acc.y = fmaf(wgt, v0.y, acc.y);
            acc.z = fmaf(wgt, v1.x, acc.z);
            acc.w = fmaf(wgt, v1.y, acc.w);
        }
    }

    const float inv = 1.f / (ssum + 1e-12f);
    const float4 r = ((const float4*)g_R)[warp * 32 + lane];
    float4 h;
    h.x = fmaf(acc.x, inv, r.x);
    h.y = fmaf(acc.y, inv, r.y);
    h.z = fmaf(acc.z, inv, r.z);
    h.w = fmaf(acc.w, inv, r.w);

    float s1 = h.x + h.y + h.z + h.w;
    float s2 = h.x * h.x + h.y * h.y + h.z * h.z + h.w * h.w;
    #pragma unroll
    for (int o = 16; o; o >>= 1) {
        s1 += __shfl_xor_sync(0xffffffffu, s1, o);
        s2 += __shfl_xor_sync(0xffffffffu, s2, o);
    }
    const float mu  = s1 * (1.f / 128.f);
    const float var = s2 * (1.f / 128.f) - mu * mu;
    const float rs  = rsqrtf(var + LN_EPS);

    const float4 g = ((const float4*)gamma)[lane];
    const float4 b = ((const float4*)beta)[lane];
    float4 o4;
    o4.x = fmaf(g.x * (h.x - mu), rs, b.x);
    o4.y = fmaf(g.y * (h.y - mu), rs, b.y);
    o4.z = fmaf(g.z * (h.z - mu), rs, b.z);
    o4.w = fmaf(g.w * (h.w - mu), rs, b.w);
    ((float4*)out)[warp * 32 + lane] = o4;
}

// ---------------- launch -------------------------------------------------------
extern "C" void kernel_launch(void* const* d_in, const int* in_sizes, int n_in,
                              void* d_out, int out_size)
{
    const float* nodes = (const float*)d_in[0];
    const float* WQ    = (const float*)d_in[1];
    const float* WK    = (const float*)d_in[2];
    const float* WV    = (const float*)d_in[3];
    const float* WR    = (const float*)d_in[4];
    const float* br    = (const float*)d_in[5];
    const float* gamma = (const float*)d_in[6];
    const float* beta  = (const float*)d_in[7];
    const int*   ei    = (const int*)d_in[8];

    const int N = in_sizes[0] / F_DIM;
    const int E = in_sizes[8] / 2;
    const int* src = ei;
    const int* dst = ei + E;

    const int nblk = (N + 15) / 16;
    const int epb  = (E + nblk - 1) / nblk;

    void* cnt_ptr = nullptr;
    cudaGetSymbolAddress(&cnt_ptr, g_counts);
    cudaMemsetAsync(cnt_ptr, 0, N * sizeof(int));

    k_qkvr<<<nblk, 128>>>(nodes, WQ, WK, WV, WR, br, dst, N, E, epb);
    k_scan<<<1, 1024>>>(N, E);
    k_scatter<<<((E + 3) / 4 + 255) / 256, 256>>>(src, dst, E);
    k_attn<<<(N + 7) / 8, 256>>>(gamma, beta, (float*)d_out, N);
}

// round 9
// speedup vs baseline: 1.2724x; 1.0903x over previous
#include <cuda_runtime.h>
#include <cuda_fp16.h>
#include <mma.h>
using namespace nvcuda;

// Problem constants (fixed by the dataset)
#define F_DIM   128
#define MAXN    10240
#define MAXE    655360
#define ATT_SCALE 0.17677669529663687f   // 1/sqrt(32)
#define LN_EPS  1e-5f
#define MBLK 64
#define NBLK 64

// ---------------- scratch (device globals; no allocation allowed) -------------
__device__ float  g_Xpad[MAXN * F_DIM];  // tf32-rounded, zero-padded X
__device__ float  g_Q[MAXN * F_DIM];
__device__ __half g_KV[MAXN * 256];      // per node: 128 K halfs then 128 V halfs
__device__ float  g_R[MAXN * F_DIM];
__device__ int    g_counts[MAXN];
__device__ int    g_offs[MAXN + 1];
__device__ int    g_cursor[MAXN];
__device__ int    g_srcsorted[MAXE];

// ---------------- K0: copy X -> tf32-rounded zero-padded buffer ----------------
__global__ void k_copyX(const float* __restrict__ X, int N, int padN) {
    const int i = blockIdx.x * 256 + threadIdx.x;
    const int node = i >> 7;
    if (node < padN)
        g_Xpad[i] = (node < N) ? wmma::__float_to_tf32(X[i]) : 0.f;
}

// ---------------- K1: tensor-core QKVR projections + dst histogram -------------
// grid = (ceil(N/64), 8). blockIdx.y picks a 64-col slice of the 512 output
// columns (4 matrices x 128). W tile staged in smem (read once per block).
// 4 warps, each computes a 16(M) x 64(N) strip via 4 wmma 16x16x8 tf32 tiles.
__global__ __launch_bounds__(128) void k_qkv_tc(
    const float* __restrict__ WQ, const float* __restrict__ WK,
    const float* __restrict__ WV, const float* __restrict__ WR,
    const float* __restrict__ br,
    const int* __restrict__ dst, int N, int E, int epb)
{
    __shared__ float Bs[128][68];        // [k][n], tf32-rounded; 34.8 KB

    const int tid  = threadIdx.x;
    const int w    = tid >> 5;
    const int lane = tid & 31;

    const int ncol0 = blockIdx.y * NBLK;
    const int mat   = ncol0 >> 7;        // 0=Q 1=K 2=V 3=R
    const int c0    = ncol0 & 127;
    const float* __restrict__ W =
        (mat == 0) ? WQ : (mat == 1) ? WK : (mat == 2) ? WV : WR;

    // stage W tile [128 x 64] into smem, tf32-rounded
    for (int i = tid; i < 128 * 64; i += 128) {
        const int f = i >> 6, c = i & 63;
        Bs[f][c] = wmma::__float_to_tf32(__ldg(&W[f * F_DIM + c0 + c]));
    }
    __syncthreads();

    const int m0 = blockIdx.x * MBLK + w * 16;
    const float* Arow = g_Xpad + m0 * F_DIM;

    wmma::fragment<wmma::accumulator, 16, 16, 8, float> acc[4];
    #pragma unroll
    for (int j = 0; j < 4; ++j) wmma::fill_fragment(acc[j], 0.f);

    #pragma unroll
    for (int k = 0; k < F_DIM; k += 8) {
        wmma::fragment<wmma::matrix_a, 16, 16, 8, wmma::precision::tf32,
                       wmma::row_major> a;
        wmma::load_matrix_sync(a, Arow + k, F_DIM);
        #pragma unroll
        for (int j = 0; j < 4; ++j) {
            wmma::fragment<wmma::matrix_b, 16, 16, 8, wmma::precision::tf32,
                           wmma::row_major> b;
            wmma::load_matrix_sync(b, &Bs[k][j * 16], 68);
            wmma::mma_sync(acc[j], a, b, acc[j]);
        }
    }

    // epilogue: stage through smem (alias Bs after barrier), typed stores
    __syncthreads();
    float* Cw = reinterpret_cast<float*>(Bs) + w * (16 * 68);
    #pragma unroll
    for (int j = 0; j < 4; ++j)
        wmma::store_matrix_sync(Cw + j * 16, acc[j], 68, wmma::mem_row_major);
    __syncwarp();

    for (int r = 0; r < 16; ++r) {
        const int node = m0 + r;
        if (node >= N) break;
        #pragma unroll
        for (int c = lane; c < 64; c += 32) {
            const float v = Cw[r * 68 + c];
            const int col = c0 + c;
            if      (mat == 0) g_Q[node * F_DIM + col] = v;
            else if (mat == 1) g_KV[node * 256 + col]       = __float2half_rn(v);
            else if (mat == 2) g_KV[node * 256 + 128 + col] = __float2half_rn(v);
            else               g_R[node * F_DIM + col] = v + __ldg(&br[col]);
        }
    }

    // fused dst histogram: this block's edge slice
    const int bid = blockIdx.y * gridDim.x + blockIdx.x;
    const int e0 = bid * epb;
    const int e1 = min(e0 + epb, E);
    for (int e = e0 + tid; e < e1; e += 128)
        atomicAdd(&g_counts[__ldg(&dst[e])], 1);
}

// ---------------- K2: exclusive scan (warp-shuffle, 2 barriers) ----------------
__global__ __launch_bounds__(1024) void k_scan(int N, int E) {
    __shared__ int wsum[32];
    const int t = threadIdx.x;
    const int lane = t & 31, w = t >> 5;
    const int base = t * 10;             // 1024*10 = 10240 >= MAXN

    int loc[10];
    int s = 0;
    #pragma unroll
    for (int i = 0; i < 10; ++i) {
        const int idx = base + i;
        loc[i] = (idx < N) ? g_counts[idx] : 0;
        s += loc[i];
    }
    int inc = s;
    #pragma unroll
    for (int o = 1; o < 32; o <<= 1) {
        int v = __shfl_up_sync(0xffffffffu, inc, o);
        if (lane >= o) inc += v;
    }
    if (lane == 31) wsum[w] = inc;
    __syncthreads();
    if (w == 0) {
        int v = wsum[lane];
        #pragma unroll
        for (int o = 1; o < 32; o <<= 1) {
            int u = __shfl_up_sync(0xffffffffu, v, o);
            if (lane >= o) v += u;
        }
        wsum[lane] = v;
    }
    __syncthreads();
    int run = ((w == 0) ? 0 : wsum[w - 1]) + (inc - s);  // exclusive prefix
    #pragma unroll
    for (int i = 0; i < 10; ++i) {
        const int idx = base + i;
        if (idx < N) { g_offs[idx] = run; g_cursor[idx] = run; run += loc[i]; }
    }
    if (t == 0) g_offs[N] = E;
}

// ---------------- K3: scatter edges into CSR order (ILP x4) --------------------
__global__ __launch_bounds__(256) void k_scatter(
    const int* __restrict__ src, const int* __restrict__ dst, int E)
{
    const int base = (blockIdx.x * blockDim.x + threadIdx.x) * 4;
    if (base + 3 < E) {
        const int4 d = *reinterpret_cast<const int4*>(dst + base);
        const int4 s = *reinterpret_cast<const int4*>(src + base);
        const int p0 = atomicAdd(&g_cursor[d.x], 1);
        const int p1 = atomicAdd(&g_cursor[d.y], 1);
        const int p2 = atomicAdd(&g_cursor[d.z], 1);
        const int p3 = atomicAdd(&g_cursor[d.w], 1);
        g_srcsorted[p0] = s.x;
        g_srcsorted[p1] = s.y;
        g_srcsorted[p2] = s.z;
        g_srcsorted[p3] = s.w;
    } else {
        for (int e = base; e < E; ++e) {
            const int pos = atomicAdd(&g_cursor[dst[e]], 1);
            g_srcsorted[pos] = src[e];
        }
    }
}

// ---------------- K4: fused attention + residual + LayerNorm (R8 version) ------
__global__ __launch_bounds__(256) void k_attn(
    const float* __restrict__ gamma, const float* __restrict__ beta,
    float* __restrict__ out, int N)
{
    const int warp = (blockIdx.x * blockDim.x + threadIdx.x) >> 5;
    if (warp >= N) return;
    const int lane = threadIdx.x & 31;

    float4 q = ((const float4*)g_Q)[warp * 32 + lane];
    q.x *= ATT_SCALE; q.y *= ATT_SCALE; q.z *= ATT_SCALE; q.w *= ATT_SCALE;

    const uint2* __restrict__ KV = (const uint2*)g_KV;   // 64 uint2 per node row

    float4 acc = make_float4(0.f, 0.f, 0.f, 0.f);
    float ssum = 0.f;

    const int beg = g_offs[warp];
    const int end = g_offs[warp + 1];

    for (int base = beg; base < end; base += 32) {
        const int idx = base + lane;
        const int mysrc = (idx < end) ? g_srcsorted[idx] : 0;
        const int cnt = min(32, end - base);
        for (int j = 0; j < cnt; ++j) {
            const int src = __shfl_sync(0xffffffffu, mysrc, j);
            const uint2 ku = KV[src * 64 + lane];
            const uint2 vu = KV[src * 64 + 32 + lane];
            const float2 k0 = __half22float2(*(const __half2*)&ku.x);
            const float2 k1 = __half22float2(*(const __half2*)&ku.y);
            float p = q.x * k0.x + q.y * k0.y + q.z * k1.x + q.w * k1.y;
            p += __shfl_xor_sync(0xffffffffu, p, 1);
            p += __shfl_xor_sync(0xffffffffu, p, 2);
            p += __shfl_xor_sync(0xffffffffu, p, 4);
            const float wgt = __expf(p);
            const float2 v0 = __half22float2(*(const __half2*)&vu.x);
            const float2 v1 = __half22float2(*(const __half2*)&vu.y);
            ssum += wgt;
            acc.x = fmaf(wgt, v0.x, acc.x);
            acc.y = fmaf(wgt, v0.y, acc.y);
            acc.z = fmaf(wgt, v1.x, acc.z);
            acc.w = fmaf(wgt, v1.y, acc.w);
        }
    }

    const float inv = 1.f / (ssum + 1e-12f);
    const float4 r = ((const float4*)g_R)[warp * 32 + lane];
    float4 h;
    h.x = fmaf(acc.x, inv, r.x);
    h.y = fmaf(acc.y, inv, r.y);
    h.z = fmaf(acc.z, inv, r.z);
    h.w = fmaf(acc.w, inv, r.w);

    float s1 = h.x + h.y + h.z + h.w;
    float s2 = h.x * h.x + h.y * h.y + h.z * h.z + h.w * h.w;
    #pragma unroll
    for (int o = 16; o; o >>= 1) {
        s1 += __shfl_xor_sync(0xffffffffu, s1, o);
        s2 += __shfl_xor_sync(0xffffffffu, s2, o);
    }
    const float mu  = s1 * (1.f / 128.f);
    const float var = s2 * (1.f / 128.f) - mu * mu;
    const float rs  = rsqrtf(var + LN_EPS);

    const float4 g = ((const float4*)gamma)[lane];
    const float4 b = ((const float4*)beta)[lane];
    float4 o4;
    o4.x = fmaf(g.x * (h.x - mu), rs, b.x);
    o4.y = fmaf(g.y * (h.y - mu), rs, b.y);
    o4.z = fmaf(g.z * (h.z - mu), rs, b.z);
    o4.w = fmaf(g.w * (h.w - mu), rs, b.w);
    ((float4*)out)[warp * 32 + lane] = o4;
}

// ---------------- launch -------------------------------------------------------
extern "C" void kernel_launch(void* const* d_in, const int* in_sizes, int n_in,
                              void* d_out, int out_size)
{
    const float* nodes = (const float*)d_in[0];
    const float* WQ    = (const float*)d_in[1];
    const float* WK    = (const float*)d_in[2];
    const float* WV    = (const float*)d_in[3];
    const float* WR    = (const float*)d_in[4];
    const float* br    = (const float*)d_in[5];
    const float* gamma = (const float*)d_in[6];
    const float* beta  = (const float*)d_in[7];
    const int*   ei    = (const int*)d_in[8];

    const int N = in_sizes[0] / F_DIM;
    const int E = in_sizes[8] / 2;
    const int* src = ei;
    const int* dst = ei + E;

    const int mblocks = (N + MBLK - 1) / MBLK;
    const int padN    = mblocks * MBLK;
    const int nblk    = mblocks * 8;
    const int epb     = (E + nblk - 1) / nblk;

    void* cnt_ptr = nullptr;
    cudaGetSymbolAddress(&cnt_ptr, g_counts);
    cudaMemsetAsync(cnt_ptr, 0, N * sizeof(int));

    k_copyX<<<(padN * F_DIM + 255) / 256, 256>>>(nodes, N, padN);
    dim3 grid_tc(mblocks, 8);
    k_qkv_tc<<<grid_tc, 128>>>(WQ, WK, WV, WR, br, dst, N, E, epb);
    k_scan<<<1, 1024>>>(N, E);
    k_scatter<<<((E + 3) / 4 + 255) / 256, 256>>>(src, dst, E);
    k_attn<<<(N + 7) / 8, 256>>>(gamma, beta, (float*)d_out, N);
}

// round 11
// speedup vs baseline: 1.3462x; 1.0580x over previous
#include <cuda_runtime.h>
#include <cuda_fp16.h>
#include <mma.h>
using namespace nvcuda;

// Problem constants (fixed by the dataset)
#define F_DIM   128
#define MAXN    10240
#define MAXE    655360
#define ATT_SCALE 0.17677669529663687f   // 1/sqrt(32)
#define LN_EPS  1e-5f
#define MBLK 64
#define NBLK 64

// ---------------- scratch (device globals; no allocation allowed) -------------
__device__ float  g_Xpad[MAXN * F_DIM];  // tf32-rounded, zero-padded X
__device__ float  g_Q[MAXN * F_DIM];
__device__ __half g_KV[MAXN * 256];      // per node: 128 K halfs then 128 V halfs
__device__ float  g_R[MAXN * F_DIM];
__device__ int    g_counts[MAXN];
__device__ int    g_offs[MAXN + 1];
__device__ int    g_rank[MAXE];          // per-edge rank within its dst segment
__device__ int    g_srcsorted[MAXE];

// ---------------- K0: copy X -> tf32-rounded zero-padded buffer ----------------
__global__ void k_copyX(const float* __restrict__ X, int N, int padN) {
    const int i = blockIdx.x * 256 + threadIdx.x;
    const int node = i >> 7;
    if (node < padN)
        g_Xpad[i] = (node < N) ? wmma::__float_to_tf32(X[i]) : 0.f;
}

// ---------------- K1: tensor-core QKVR projections + dst histogram+rank --------
// grid = (ceil(N/64), 8). blockIdx.y picks a 64-col slice of the 512 output
// columns (4 matrices x 128). W tile staged in smem (read once per block).
// 4 warps, each computes a 16(M) x 64(N) strip via 4 wmma 16x16x8 tf32 tiles.
// Tail: histogram of dst; the atomicAdd return value IS the edge's segment rank.
__global__ __launch_bounds__(128) void k_qkv_tc(
    const float* __restrict__ WQ, const float* __restrict__ WK,
    const float* __restrict__ WV, const float* __restrict__ WR,
    const float* __restrict__ br,
    const int* __restrict__ dst, int N, int E, int epb)
{
    __shared__ float Bs[128][68];        // [k][n], tf32-rounded; 34.8 KB

    const int tid  = threadIdx.x;
    const int w    = tid >> 5;
    const int lane = tid & 31;

    const int ncol0 = blockIdx.y * NBLK;
    const int mat   = ncol0 >> 7;        // 0=Q 1=K 2=V 3=R
    const int c0    = ncol0 & 127;
    const float* __restrict__ W =
        (mat == 0) ? WQ : (mat == 1) ? WK : (mat == 2) ? WV : WR;

    // stage W tile [128 x 64] into smem, tf32-rounded
    for (int i = tid; i < 128 * 64; i += 128) {
        const int f = i >> 6, c = i & 63;
        Bs[f][c] = wmma::__float_to_tf32(__ldg(&W[f * F_DIM + c0 + c]));
    }
    __syncthreads();

    const int m0 = blockIdx.x * MBLK + w * 16;
    const float* Arow = g_Xpad + m0 * F_DIM;

    wmma::fragment<wmma::accumulator, 16, 16, 8, float> acc[4];
    #pragma unroll
    for (int j = 0; j < 4; ++j) wmma::fill_fragment(acc[j], 0.f);

    #pragma unroll
    for (int k = 0; k < F_DIM; k += 8) {
        wmma::fragment<wmma::matrix_a, 16, 16, 8, wmma::precision::tf32,
                       wmma::row_major> a;
        wmma::load_matrix_sync(a, Arow + k, F_DIM);
        #pragma unroll
        for (int j = 0; j < 4; ++j) {
            wmma::fragment<wmma::matrix_b, 16, 16, 8, wmma::precision::tf32,
                           wmma::row_major> b;
            wmma::load_matrix_sync(b, &Bs[k][j * 16], 68);
            wmma::mma_sync(acc[j], a, b, acc[j]);
        }
    }

    // epilogue: stage through smem (alias Bs after barrier), typed stores
    __syncthreads();
    float* Cw = reinterpret_cast<float*>(Bs) + w * (16 * 68);
    #pragma unroll
    for (int j = 0; j < 4; ++j)
        wmma::store_matrix_sync(Cw + j * 16, acc[j], 68, wmma::mem_row_major);
    __syncwarp();

    for (int r = 0; r < 16; ++r) {
        const int node = m0 + r;
        if (node >= N) break;
        #pragma unroll
        for (int c = lane; c < 64; c += 32) {
            const float v = Cw[r * 68 + c];
            const int col = c0 + c;
            if      (mat == 0) g_Q[node * F_DIM + col] = v;
            else if (mat == 1) g_KV[node * 256 + col]       = __float2half_rn(v);
            else if (mat == 2) g_KV[node * 256 + 128 + col] = __float2half_rn(v);
            else               g_R[node * F_DIM + col] = v + __ldg(&br[col]);
        }
    }

    // fused dst histogram + rank capture: this block's edge slice
    const int bid = blockIdx.y * gridDim.x + blockIdx.x;
    const int e0 = bid * epb;
    const int e1 = min(e0 + epb, E);
    for (int e = e0 + tid; e < e1; e += 128)
        g_rank[e] = atomicAdd(&g_counts[__ldg(&dst[e])], 1);
}

// ---------------- K2: exclusive scan (warp-shuffle, 2 barriers) ----------------
__global__ __launch_bounds__(1024) void k_scan(int N, int E) {
    __shared__ int wsum[32];
    const int t = threadIdx.x;
    const int lane = t & 31, w = t >> 5;
    const int base = t * 10;             // 1024*10 = 10240 >= MAXN

    int loc[10];
    int s = 0;
    #pragma unroll
    for (int i = 0; i < 10; ++i) {
        const int idx = base + i;
        loc[i] = (idx < N) ? g_counts[idx] : 0;
        s += loc[i];
    }
    int inc = s;
    #pragma unroll
    for (int o = 1; o < 32; o <<= 1) {
        int v = __shfl_up_sync(0xffffffffu, inc, o);
        if (lane >= o) inc += v;
    }
    if (lane == 31) wsum[w] = inc;
    __syncthreads();
    if (w == 0) {
        int v = wsum[lane];
        #pragma unroll
        for (int o = 1; o < 32; o <<= 1) {
            int u = __shfl_up_sync(0xffffffffu, v, o);
            if (lane >= o) v += u;
        }
        wsum[lane] = v;
    }
    __syncthreads();
    int run = ((w == 0) ? 0 : wsum[w - 1]) + (inc - s);  // exclusive prefix
    #pragma unroll
    for (int i = 0; i < 10; ++i) {
        const int idx = base + i;
        if (idx < N) g_offs[idx] = run, run += loc[i];
    }
    if (t == 0) g_offs[N] = E;
}

// ---------------- K3: scatter edges into CSR order (NO atomics) ----------------
// pos = offs[dst] + rank (rank captured during histogram). Pure streaming.
__global__ __launch_bounds__(256) void k_scatter(
    const int* __restrict__ src, const int* __restrict__ dst, int E)
{
    const int base = (blockIdx.x * blockDim.x + threadIdx.x) * 4;
    if (base + 3 < E) {
        const int4 d = *reinterpret_cast<const int4*>(dst + base);
        const int4 s = *reinterpret_cast<const int4*>(src + base);
        const int4 r = *reinterpret_cast<const int4*>(g_rank + base);
        g_srcsorted[g_offs[d.x] + r.x] = s.x;
        g_srcsorted[g_offs[d.y] + r.y] = s.y;
        g_srcsorted[g_offs[d.z] + r.z] = s.z;
        g_srcsorted[g_offs[d.w] + r.w] = s.w;
    } else {
        for (int e = base; e < E; ++e)
            g_srcsorted[g_offs[dst[e]] + g_rank[e]] = src[e];
    }
}

// ---------------- K4: fused attention + residual + LayerNorm (R8/R9 version) ---
__global__ __launch_bounds__(256) void k_attn(
    const float* __restrict__ gamma, const float* __restrict__ beta,
    float* __restrict__ out, int N)
{
    const int warp = (blockIdx.x * blockDim.x + threadIdx.x) >> 5;
    if (warp >= N) return;
    const int lane = threadIdx.x & 31;

    float4 q = ((const float4*)g_Q)[warp * 32 + lane];
    q.x *= ATT_SCALE; q.y *= ATT_SCALE; q.z *= ATT_SCALE; q.w *= ATT_SCALE;

    const uint2* __restrict__ KV = (const uint2*)g_KV;   // 64 uint2 per node row

    float4 acc = make_float4(0.f, 0.f, 0.f, 0.f);
    float ssum = 0.f;

    const int beg = g_offs[warp];
    const int end = g_offs[warp + 1];

    for (int base = beg; base < end; base += 32) {
        const int idx = base + lane;
        const int mysrc = (idx < end) ? g_srcsorted[idx] : 0;
        const int cnt = min(32, end - base);
        for (int j = 0; j < cnt; ++j) {
            const int src = __shfl_sync(0xffffffffu, mysrc, j);
            const uint2 ku = KV[src * 64 + lane];
            const uint2 vu = KV[src * 64 + 32 + lane];
            const float2 k0 = __half22float2(*(const __half2*)&ku.x);
            const float2 k1 = __half22float2(*(const __half2*)&ku.y);
            float p = q.x * k0.x + q.y * k0.y + q.z * k1.x + q.w * k1.y;
            p += __shfl_xor_sync(0xffffffffu, p, 1);
            p += __shfl_xor_sync(0xffffffffu, p, 2);
            p += __shfl_xor_sync(0xffffffffu, p, 4);
            const float wgt = __expf(p);
            const float2 v0 = __half22float2(*(const __half2*)&vu.x);
            const float2 v1 = __half22float2(*(const __half2*)&vu.y);
            ssum += wgt;
            acc.x = fmaf(wgt, v0.x, acc.x);
            acc.y = fmaf(wgt, v0.y, acc.y);
            acc.z = fmaf(wgt, v1.x, acc.z);
            acc.w = fmaf(wgt, v1.y, acc.w);
        }
    }

    const float inv = 1.f / (ssum + 1e-12f);
    const float4 r = ((const float4*)g_R)[warp * 32 + lane];
    float4 h;
    h.x = fmaf(acc.x, inv, r.x);
    h.y = fmaf(acc.y, inv, r.y);
    h.z = fmaf(acc.z, inv, r.z);
    h.w = fmaf(acc.w, inv, r.w);

    float s1 = h.x + h.y + h.z + h.w;
    float s2 = h.x * h.x + h.y * h.y + h.z * h.z + h.w * h.w;
    #pragma unroll
    for (int o = 16; o; o >>= 1) {
        s1 += __shfl_xor_sync(0xffffffffu, s1, o);
        s2 += __shfl_xor_sync(0xffffffffu, s2, o);
    }
    const float mu  = s1 * (1.f / 128.f);
    const float var = s2 * (1.f / 128.f) - mu * mu;
    const float rs  = rsqrtf(var + LN_EPS);

    const float4 g = ((const float4*)gamma)[lane];
    const float4 b = ((const float4*)beta)[lane];
    float4 o4;
    o4.x = fmaf(g.x * (h.x - mu), rs, b.x);
    o4.y = fmaf(g.y * (h.y - mu), rs, b.y);
    o4.z = fmaf(g.z * (h.z - mu), rs, b.z);
    o4.w = fmaf(g.w * (h.w - mu), rs, b.w);
    ((float4*)out)[warp * 32 + lane] = o4;
}

// ---------------- launch -------------------------------------------------------
extern "C" void kernel_launch(void* const* d_in, const int* in_sizes, int n_in,
                              void* d_out, int out_size)
{
    const float* nodes = (const float*)d_in[0];
    const float* WQ    = (const float*)d_in[1];
    const float* WK    = (const float*)d_in[2];
    const float* WV    = (const float*)d_in[3];
    const float* WR    = (const float*)d_in[4];
    const float* br    = (const float*)d_in[5];
    const float* gamma = (const float*)d_in[6];
    const float* beta  = (const float*)d_in[7];
    const int*   ei    = (const int*)d_in[8];

    const int N = in_sizes[0] / F_DIM;
    const int E = in_sizes[8] / 2;
    const int* src = ei;
    const int* dst = ei + E;

    const int mblocks = (N + MBLK - 1) / MBLK;
    const int padN    = mblocks * MBLK;
    const int nblk    = mblocks * 8;
    const int epb     = (E + nblk - 1) / nblk;

    void* cnt_ptr = nullptr;
    cudaGetSymbolAddress(&cnt_ptr, g_counts);
    cudaMemsetAsync(cnt_ptr, 0, N * sizeof(int));

    k_copyX<<<(padN * F_DIM + 255) / 256, 256>>>(nodes, N, padN);
    dim3 grid_tc(mblocks, 8);
    k_qkv_tc<<<grid_tc, 128>>>(WQ, WK, WV, WR, br, dst, N, E, epb);
    k_scan<<<1, 1024>>>(N, E);
    k_scatter<<<((E + 3) / 4 + 255) / 256, 256>>>(src, dst, E);
    k_attn<<<(N + 7) / 8, 256>>>(gamma, beta, (float*)d_out, N);
}